// round 1
// baseline (speedup 1.0000x reference)
#include <cuda_runtime.h>

#define BMAX 8192
#define NSTEPS 50
#define LRATE 0.1f

// Scratch for nearest-neighbor result (no cudaMalloc allowed).
__device__ float g_c0[BMAX];

// ---------------------------------------------------------------------------
// Kernel 1: 1-D nearest neighbor, one warp per query i.
// Matches reference exactly: d = sqrt((ci-cj)^2), diagonal +1e9,
// argmin with first-index tiebreak.
// ---------------------------------------------------------------------------
__global__ void nn_kernel(const float* __restrict__ c, int B) {
    int warp = (blockIdx.x * blockDim.x + threadIdx.x) >> 5;
    int lane = threadIdx.x & 31;
    if (warp >= B) return;
    float ci = c[warp];
    float bestD = 3.0e38f;
    int bestJ = 0;
    for (int j = lane; j < B; j += 32) {
        float dt = ci - c[j];
        float d = __fsqrt_rn(__fmul_rn(dt, dt));
        if (j == warp) d += 1e9f;            // reference adds eye*1e9
        if (d < bestD) { bestD = d; bestJ = j; }   // ascending j -> keeps first
    }
#pragma unroll
    for (int off = 16; off; off >>= 1) {
        float dO = __shfl_down_sync(0xffffffffu, bestD, off);
        int   jO = __shfl_down_sync(0xffffffffu, bestJ, off);
        if (dO < bestD || (dO == bestD && jO < bestJ)) { bestD = dO; bestJ = jO; }
    }
    if (lane == 0) g_c0[warp] = c[bestJ];
}

// ---------------------------------------------------------------------------
// Kernel 2: 50-step gradient descent on y, per sample.
//   z1 = a + w1y*y ; h1 = relu ; z2 = W2 h1 + b2 ; h2 = relu ;
//   z3 = W3 h2 + b3 ; g3 = (z3>0)*W4 ; g2 = (z2>0)*(W3^T g3) ;
//   g1 = (z1>0)*(W2^T g2) ; gy = sum(w1y * g1) ; y -= 0.1*gy
// Layout: 64 threads per sample-PAIR (thread t = neuron t, 2 samples A/B),
// 256-thread block = 4 groups = 8 samples. Weights in shared, float4-blocked,
// with explicit transposed copies so both directions use coalesced LDS.128.
// ---------------------------------------------------------------------------
__global__ __launch_bounds__(256) void solver_kernel(
    const float* __restrict__ x,
    const float* __restrict__ W1, const float* __restrict__ b1,
    const float* __restrict__ W2, const float* __restrict__ b2,
    const float* __restrict__ W3, const float* __restrict__ b3,
    const float* __restrict__ W4,
    float* __restrict__ out, int B)
{
    extern __shared__ float4 sm4[];
    float4* W2v = sm4;              // [16*64]  W2v[m*64+t] = W2[t][4m..4m+3]
    float4* W2t = sm4 + 1024;       // [16*64]  W2t[m*64+t] = W2[4m..4m+3][t]
    float4* W3v = sm4 + 2048;
    float4* W3t = sm4 + 3072;
    float*  F   = (float*)(sm4 + 4096);
    float* h1b = F;                 // [8][64]
    float* h2b = F + 512;           // [8][64]
    float* g3b = F + 1024;          // [8][64]
    float* g2b = F + 1536;          // [8][64]
    float* red = F + 2048;          // [8][2]

    int tid = threadIdx.x;

    // Load forward copies (coalesced float4 from global)
    for (int idx = tid; idx < 1024; idx += 256) {
        int m = idx >> 6, t = idx & 63;
        W2v[idx] = *(const float4*)(W2 + t * 64 + m * 4);
        W3v[idx] = *(const float4*)(W3 + t * 64 + m * 4);
    }
    __syncthreads();
    // Build transposed copies from shared
    {
        const float* W2f = (const float*)W2v;
        const float* W3f = (const float*)W3v;
        for (int idx = tid; idx < 1024; idx += 256) {
            int m = idx >> 6, t = idx & 63;
            int base = ((t >> 2) << 8) + (t & 3);   // float index of W2[0][t] pattern
            float4 a, b;
            a.x = W2f[base + ((4 * m + 0) << 2)];
            a.y = W2f[base + ((4 * m + 1) << 2)];
            a.z = W2f[base + ((4 * m + 2) << 2)];
            a.w = W2f[base + ((4 * m + 3) << 2)];
            W2t[idx] = a;
            b.x = W3f[base + ((4 * m + 0) << 2)];
            b.y = W3f[base + ((4 * m + 1) << 2)];
            b.z = W3f[base + ((4 * m + 2) << 2)];
            b.w = W3f[base + ((4 * m + 3) << 2)];
            W3t[idx] = b;
        }
    }
    __syncthreads();

    int g = tid >> 6;            // group 0..3
    int t = tid & 63;            // neuron index
    int s0 = blockIdx.x * 8 + g * 2;
    int s1 = s0 + 1;

    float w1y = W1[t * 3 + 1];
    float b1t = b1[t];
    float aA = fmaf(W1[t * 3 + 0], x[s0], fmaf(W1[t * 3 + 2], g_c0[s0], b1t));
    float aB = fmaf(W1[t * 3 + 0], x[s1], fmaf(W1[t * 3 + 2], g_c0[s1], b1t));
    float b2t = b2[t], b3t = b3[t], W4t = W4[t];

    float* h1A = h1b + g * 128; float* h1B = h1A + 64;
    float* h2A = h2b + g * 128; float* h2B = h2A + 64;
    float* g3A = g3b + g * 128; float* g3B = g3A + 64;
    float* g2A = g2b + g * 128; float* g2B = g2A + 64;

    float yA = 0.f, yB = 0.f;

    for (int step = 0; step < NSTEPS; step++) {
        // layer 1 (rank-1 in y)
        float z1A = fmaf(w1y, yA, aA);
        float z1B = fmaf(w1y, yB, aB);
        bool m1A = z1A > 0.f, m1B = z1B > 0.f;
        h1A[t] = m1A ? z1A : 0.f;
        h1B[t] = m1B ? z1B : 0.f;
        __syncthreads();

        // layer 2 forward
        float z2A = b2t, z2B = b2t;
        {
            const float4* hA4 = (const float4*)h1A;
            const float4* hB4 = (const float4*)h1B;
#pragma unroll
            for (int m = 0; m < 16; m++) {
                float4 w = W2v[(m << 6) + t];
                float4 hA = hA4[m], hB = hB4[m];
                z2A = fmaf(w.x, hA.x, z2A); z2A = fmaf(w.y, hA.y, z2A);
                z2A = fmaf(w.z, hA.z, z2A); z2A = fmaf(w.w, hA.w, z2A);
                z2B = fmaf(w.x, hB.x, z2B); z2B = fmaf(w.y, hB.y, z2B);
                z2B = fmaf(w.z, hB.z, z2B); z2B = fmaf(w.w, hB.w, z2B);
            }
        }
        bool m2A = z2A > 0.f, m2B = z2B > 0.f;
        h2A[t] = m2A ? z2A : 0.f;
        h2B[t] = m2B ? z2B : 0.f;
        __syncthreads();

        // layer 3 forward -> g3 seed
        float z3A = b3t, z3B = b3t;
        {
            const float4* hA4 = (const float4*)h2A;
            const float4* hB4 = (const float4*)h2B;
#pragma unroll
            for (int m = 0; m < 16; m++) {
                float4 w = W3v[(m << 6) + t];
                float4 hA = hA4[m], hB = hB4[m];
                z3A = fmaf(w.x, hA.x, z3A); z3A = fmaf(w.y, hA.y, z3A);
                z3A = fmaf(w.z, hA.z, z3A); z3A = fmaf(w.w, hA.w, z3A);
                z3B = fmaf(w.x, hB.x, z3B); z3B = fmaf(w.y, hB.y, z3B);
                z3B = fmaf(w.z, hB.z, z3B); z3B = fmaf(w.w, hB.w, z3B);
            }
        }
        g3A[t] = (z3A > 0.f) ? W4t : 0.f;
        g3B[t] = (z3B > 0.f) ? W4t : 0.f;
        __syncthreads();

        // backward layer 3: g2 = m2 * (W3^T g3)
        float s2A = 0.f, s2B = 0.f;
        {
            const float4* gA4 = (const float4*)g3A;
            const float4* gB4 = (const float4*)g3B;
#pragma unroll
            for (int m = 0; m < 16; m++) {
                float4 w = W3t[(m << 6) + t];
                float4 gA = gA4[m], gB = gB4[m];
                s2A = fmaf(w.x, gA.x, s2A); s2A = fmaf(w.y, gA.y, s2A);
                s2A = fmaf(w.z, gA.z, s2A); s2A = fmaf(w.w, gA.w, s2A);
                s2B = fmaf(w.x, gB.x, s2B); s2B = fmaf(w.y, gB.y, s2B);
                s2B = fmaf(w.z, gB.z, s2B); s2B = fmaf(w.w, gB.w, s2B);
            }
        }
        g2A[t] = m2A ? s2A : 0.f;
        g2B[t] = m2B ? s2B : 0.f;
        __syncthreads();

        // backward layer 2: g1 = m1 * (W2^T g2);  gy = sum(w1y * g1)
        float s1Av = 0.f, s1Bv = 0.f;
        {
            const float4* gA4 = (const float4*)g2A;
            const float4* gB4 = (const float4*)g2B;
#pragma unroll
            for (int m = 0; m < 16; m++) {
                float4 w = W2t[(m << 6) + t];
                float4 gA = gA4[m], gB = gB4[m];
                s1Av = fmaf(w.x, gA.x, s1Av); s1Av = fmaf(w.y, gA.y, s1Av);
                s1Av = fmaf(w.z, gA.z, s1Av); s1Av = fmaf(w.w, gA.w, s1Av);
                s1Bv = fmaf(w.x, gB.x, s1Bv); s1Bv = fmaf(w.y, gB.y, s1Bv);
                s1Bv = fmaf(w.z, gB.z, s1Bv); s1Bv = fmaf(w.w, gB.w, s1Bv);
            }
        }
        float pA = m1A ? w1y * s1Av : 0.f;
        float pB = m1B ? w1y * s1Bv : 0.f;
#pragma unroll
        for (int off = 16; off; off >>= 1) {
            pA += __shfl_xor_sync(0xffffffffu, pA, off);
            pB += __shfl_xor_sync(0xffffffffu, pB, off);
        }
        if ((t & 31) == 0) {
            int half = t >> 5;
            red[(g * 2 + 0) * 2 + half] = pA;
            red[(g * 2 + 1) * 2 + half] = pB;
        }
        __syncthreads();
        yA -= LRATE * (red[(g * 2 + 0) * 2] + red[(g * 2 + 0) * 2 + 1]);
        yB -= LRATE * (red[(g * 2 + 1) * 2] + red[(g * 2 + 1) * 2 + 1]);
    }

    if (t == 0) { out[s0] = yA; out[s1] = yB; }
}

// ---------------------------------------------------------------------------
// Launch
// ---------------------------------------------------------------------------
extern "C" void kernel_launch(void* const* d_in, const int* in_sizes, int n_in,
                              void* d_out, int out_size) {
    const float* x  = (const float*)d_in[0];
    const float* c  = (const float*)d_in[1];
    const float* W1 = (const float*)d_in[2];
    const float* b1 = (const float*)d_in[3];
    const float* W2 = (const float*)d_in[4];
    const float* b2 = (const float*)d_in[5];
    const float* W3 = (const float*)d_in[6];
    const float* b3 = (const float*)d_in[7];
    const float* W4 = (const float*)d_in[8];
    // d_in[9] = b4 : constant offset, drops out of the y-gradient
    float* out = (float*)d_out;
    int B = in_sizes[0];

    const int SMEM = 4096 * 16 + (2048 + 16) * 4;  // 73792 bytes
    cudaFuncSetAttribute(solver_kernel,
                         cudaFuncAttributeMaxDynamicSharedMemorySize, SMEM);

    nn_kernel<<<(B * 32 + 255) / 256, 256>>>(c, B);
    solver_kernel<<<B / 8, 256, SMEM>>>(x, W1, b1, W2, b2, W3, b3, W4, out, B);
}

// round 2
// speedup vs baseline: 1.1999x; 1.1999x over previous
#include <cuda_runtime.h>

#define NSTEPS 50
#define LRATE  0.1f
#define BMAX   8192

__device__ float g_c0[BMAX];

// ---------------------------------------------------------------------------
// packed f32x2 helpers (Blackwell FFMA2). Lane order: lo = lower address float.
// ---------------------------------------------------------------------------
typedef unsigned long long u64;

__device__ __forceinline__ u64 pk2(float lo, float hi) {
    u64 r; asm("mov.b64 %0, {%1,%2};" : "=l"(r) : "f"(lo), "f"(hi)); return r;
}
__device__ __forceinline__ void upk2(u64 v, float& lo, float& hi) {
    asm("mov.b64 {%0,%1}, %2;" : "=f"(lo), "=f"(hi) : "l"(v));
}
__device__ __forceinline__ void fma2(u64& d, u64 a, u64 b) {
    asm("fma.rn.f32x2 %0, %1, %2, %0;" : "+l"(d) : "l"(a), "l"(b));
}

// ---------------------------------------------------------------------------
// Kernel 1: 1-D nearest neighbor. sqrt((ci-cj)^2) == |ci-cj| exactly in RN
// fp32, so use fabsf (no MUFU). c tiled through shared. One warp per query.
// ---------------------------------------------------------------------------
#define NN_TILE 2048
__global__ __launch_bounds__(256) void nn_kernel(const float* __restrict__ c, int B) {
    __shared__ float ct[NN_TILE];
    int lane = threadIdx.x & 31;
    int w    = threadIdx.x >> 5;
    int q    = blockIdx.x * 8 + w;
    float cq = (q < B) ? c[q] : 0.f;
    float bestD = 3.0e38f; int bestJ = 0;
    for (int t0 = 0; t0 < B; t0 += NN_TILE) {
        int nt = min(NN_TILE, B - t0);
        __syncthreads();
        for (int i = threadIdx.x; i < nt; i += 256) ct[i] = c[t0 + i];
        __syncthreads();
        for (int jj = lane; jj < nt; jj += 32) {
            int j = t0 + jj;
            float d = fabsf(cq - ct[jj]);
            if (j == q) d += 1e9f;                        // diagonal mask
            if (d < bestD) { bestD = d; bestJ = j; }      // keeps first index
        }
    }
#pragma unroll
    for (int off = 16; off; off >>= 1) {
        float dO = __shfl_down_sync(0xffffffffu, bestD, off);
        int   jO = __shfl_down_sync(0xffffffffu, bestJ, off);
        if (dO < bestD || (dO == bestD && jO < bestJ)) { bestD = dO; bestJ = jO; }
    }
    if (lane == 0 && q < B) g_c0[q] = c[bestJ];
}

// ---------------------------------------------------------------------------
// Kernel 2: block = 64 neurons x 32 samples, 256 threads, 4n x 2s tile/thread.
// Forward layout W?T[k][n] (padded stride 68), backward natural W?N[j][n].
// Activations stored duplicated {v,v} as u64 -> inner loop: 2 LDS.128 + 4 FFMA2.
// ---------------------------------------------------------------------------
__global__ __launch_bounds__(256, 2) void solver_kernel(
    const float* __restrict__ x,
    const float* __restrict__ W1, const float* __restrict__ b1,
    const float* __restrict__ W2, const float* __restrict__ b2,
    const float* __restrict__ W3, const float* __restrict__ b3,
    const float* __restrict__ W4,
    float* __restrict__ out)
{
    extern __shared__ __align__(16) char smraw[];
    float* W2T = (float*)smraw;            // [64][68]
    float* W3T = W2T + 64 * 68;            // [64][68]
    float* W2N = W3T + 64 * 68;            // [64][64]
    float* W3N = W2N + 64 * 64;            // [64][64]
    u64*  BufA = (u64*)(W3N + 64 * 64);    // [64][32] dup pairs (h1 / g3)
    u64*  BufB = BufA + 64 * 32;           // [64][32] dup pairs (h2 / g2)
    float* red = (float*)(BufB + 64 * 32); // [16][32]
    float* ysm = red + 16 * 32;            // [32]

    int tid = threadIdx.x;

    // natural weight copies (coalesced float4)
    for (int i = tid; i < 1024; i += 256) {
        ((float4*)W2N)[i] = ((const float4*)W2)[i];
        ((float4*)W3N)[i] = ((const float4*)W3)[i];
    }
    __syncthreads();
    // transposed copies from shared: read conflict-free, write 4-way (one-time)
    for (int i = tid; i < 4096; i += 256) {
        int n = i >> 6, k = i & 63;
        W2T[k * 68 + n] = W2N[i];
        W3T[k * 68 + n] = W3N[i];
    }
    if (tid < 32) ysm[tid] = 0.f;          // y0 = Y_MEAN = 0

    int sT = tid & 15, nT = tid >> 4;
    int s0 = 2 * sT;                       // local samples s0, s0+1
    int n0 = 4 * nT;                       // neurons n0..n0+3
    int gs = blockIdx.x * 32;

    float xs0 = x[gs + s0],     xs1 = x[gs + s0 + 1];
    float c00 = g_c0[gs + s0],  c01 = g_c0[gs + s0 + 1];

    float a[8], w1y[4];
#pragma unroll
    for (int r = 0; r < 4; r++) {
        int n = n0 + r;
        float w1x = W1[n * 3 + 0]; w1y[r] = W1[n * 3 + 1];
        float w1c = W1[n * 3 + 2]; float bb = b1[n];
        a[r * 2 + 0] = fmaf(w1x, xs0, fmaf(w1c, c00, bb));
        a[r * 2 + 1] = fmaf(w1x, xs1, fmaf(w1c, c01, bb));
    }
    u64 bp2_0 = pk2(b2[n0], b2[n0 + 1]), bp2_1 = pk2(b2[n0 + 2], b2[n0 + 3]);
    u64 bp3_0 = pk2(b3[n0], b3[n0 + 1]), bp3_1 = pk2(b3[n0 + 2], b3[n0 + 3]);
    float w4r[4] = { W4[n0], W4[n0 + 1], W4[n0 + 2], W4[n0 + 3] };
    __syncthreads();

    for (int step = 0; step < NSTEPS; step++) {
        float y0 = ysm[s0], y1 = ysm[s0 + 1];

        // ---- layer 1 (rank-1 in y) -> h1 dup ----
        float z1v[8];
#pragma unroll
        for (int r = 0; r < 4; r++) {
            float za = fmaf(w1y[r], y0, a[r * 2 + 0]);
            float zb = fmaf(w1y[r], y1, a[r * 2 + 1]);
            z1v[r * 2 + 0] = za; z1v[r * 2 + 1] = zb;
            float ha = fmaxf(za, 0.f), hb = fmaxf(zb, 0.f);
            BufA[(n0 + r) * 32 + s0]     = pk2(ha, ha);
            BufA[(n0 + r) * 32 + s0 + 1] = pk2(hb, hb);
        }
        __syncthreads();

        // ---- fwd2: z2 = W2 h1 + b2 ----
        u64 A00 = bp2_0, A01 = bp2_0, A10 = bp2_1, A11 = bp2_1;
#pragma unroll 16
        for (int k = 0; k < 64; k++) {
            ulonglong2 w = *(const ulonglong2*)(W2T + k * 68 + n0);
            ulonglong2 h = *(const ulonglong2*)(BufA + k * 32 + s0);
            fma2(A00, w.x, h.x); fma2(A01, w.x, h.y);
            fma2(A10, w.y, h.x); fma2(A11, w.y, h.y);
        }
        float z2v[8];
        upk2(A00, z2v[0], z2v[2]); upk2(A01, z2v[1], z2v[3]);
        upk2(A10, z2v[4], z2v[6]); upk2(A11, z2v[5], z2v[7]);
#pragma unroll
        for (int e = 0; e < 8; e++) {
            float h = fmaxf(z2v[e], 0.f);
            BufB[(n0 + (e >> 1)) * 32 + s0 + (e & 1)] = pk2(h, h);
        }
        __syncthreads();

        // ---- fwd3: z3 = W3 h2 + b3 -> g3 = (z3>0)*W4 ----
        u64 B00 = bp3_0, B01 = bp3_0, B10 = bp3_1, B11 = bp3_1;
#pragma unroll 16
        for (int k = 0; k < 64; k++) {
            ulonglong2 w = *(const ulonglong2*)(W3T + k * 68 + n0);
            ulonglong2 h = *(const ulonglong2*)(BufB + k * 32 + s0);
            fma2(B00, w.x, h.x); fma2(B01, w.x, h.y);
            fma2(B10, w.y, h.x); fma2(B11, w.y, h.y);
        }
        float z3v[8];
        upk2(B00, z3v[0], z3v[2]); upk2(B01, z3v[1], z3v[3]);
        upk2(B10, z3v[4], z3v[6]); upk2(B11, z3v[5], z3v[7]);
#pragma unroll
        for (int e = 0; e < 8; e++) {
            float g = (z3v[e] > 0.f) ? w4r[e >> 1] : 0.f;
            BufA[(n0 + (e >> 1)) * 32 + s0 + (e & 1)] = pk2(g, g);
        }
        __syncthreads();

        // ---- bwd3: g2 = m2 .* (W3^T g3) ----
        u64 C00 = 0, C01 = 0, C10 = 0, C11 = 0;
#pragma unroll 16
        for (int j = 0; j < 64; j++) {
            ulonglong2 w = *(const ulonglong2*)(W3N + j * 64 + n0);
            ulonglong2 g = *(const ulonglong2*)(BufA + j * 32 + s0);
            fma2(C00, w.x, g.x); fma2(C01, w.x, g.y);
            fma2(C10, w.y, g.x); fma2(C11, w.y, g.y);
        }
        float s2v[8];
        upk2(C00, s2v[0], s2v[2]); upk2(C01, s2v[1], s2v[3]);
        upk2(C10, s2v[4], s2v[6]); upk2(C11, s2v[5], s2v[7]);
#pragma unroll
        for (int e = 0; e < 8; e++) {
            float g = (z2v[e] > 0.f) ? s2v[e] : 0.f;
            BufB[(n0 + (e >> 1)) * 32 + s0 + (e & 1)] = pk2(g, g);
        }
        __syncthreads();

        // ---- bwd2: g1 = m1 .* (W2^T g2);  gy = sum_n w1y[n] g1[n] ----
        u64 D00 = 0, D01 = 0, D10 = 0, D11 = 0;
#pragma unroll 16
        for (int j = 0; j < 64; j++) {
            ulonglong2 w = *(const ulonglong2*)(W2N + j * 64 + n0);
            ulonglong2 g = *(const ulonglong2*)(BufB + j * 32 + s0);
            fma2(D00, w.x, g.x); fma2(D01, w.x, g.y);
            fma2(D10, w.y, g.x); fma2(D11, w.y, g.y);
        }
        float s1v[8];
        upk2(D00, s1v[0], s1v[2]); upk2(D01, s1v[1], s1v[3]);
        upk2(D10, s1v[4], s1v[6]); upk2(D11, s1v[5], s1v[7]);
        float pg0 = 0.f, pg1 = 0.f;
#pragma unroll
        for (int r = 0; r < 4; r++) {
            float ga = (z1v[r * 2 + 0] > 0.f) ? s1v[r * 2 + 0] : 0.f;
            float gb = (z1v[r * 2 + 1] > 0.f) ? s1v[r * 2 + 1] : 0.f;
            pg0 = fmaf(w1y[r], ga, pg0);
            pg1 = fmaf(w1y[r], gb, pg1);
        }
        red[nT * 32 + s0]     = pg0;
        red[nT * 32 + s0 + 1] = pg1;
        __syncthreads();

        if (tid < 32) {
            float s = 0.f;
#pragma unroll
            for (int q = 0; q < 16; q++) s += red[q * 32 + tid];
            ysm[tid] -= LRATE * s;
        }
        __syncthreads();
    }

    if (tid < 32) out[gs + tid] = ysm[tid];
}

// ---------------------------------------------------------------------------
// Launch
// ---------------------------------------------------------------------------
extern "C" void kernel_launch(void* const* d_in, const int* in_sizes, int n_in,
                              void* d_out, int out_size) {
    const float* x  = (const float*)d_in[0];
    const float* c  = (const float*)d_in[1];
    const float* W1 = (const float*)d_in[2];
    const float* b1 = (const float*)d_in[3];
    const float* W2 = (const float*)d_in[4];
    const float* b2 = (const float*)d_in[5];
    const float* W3 = (const float*)d_in[6];
    const float* b3 = (const float*)d_in[7];
    const float* W4 = (const float*)d_in[8];
    // d_in[9] = b4: constant offset, no effect on dE/dy
    float* out = (float*)d_out;
    int B = in_sizes[0];

    // smem: 2*64*68*4 + 2*64*64*4 + 2*64*32*8 + 16*32*4 + 32*4 = 102528 B
    const int SMEM = 2 * 64 * 68 * 4 + 2 * 64 * 64 * 4 + 2 * 64 * 32 * 8
                   + 16 * 32 * 4 + 32 * 4;
    cudaFuncSetAttribute(solver_kernel,
                         cudaFuncAttributeMaxDynamicSharedMemorySize, SMEM);

    nn_kernel<<<(B + 7) / 8, 256>>>(c, B);
    solver_kernel<<<B / 32, 256, SMEM>>>(x, W1, b1, W2, b2, W3, b3, W4, out);
}